// round 7
// baseline (speedup 1.0000x reference)
#include <cuda_runtime.h>
#include <cuda_fp16.h>
#include <math.h>
#include <stdint.h>

#define NN   8192
#define DIN  256
#define DOUT 128
#define TI   32
#define JS   4              // j segments
#define SEG  (NN / JS)      // 2048
#define KC   64             // j per chunk
#define NCH  (SEG / KC)     // 32
#define RT   64             // i-rows per CTA tile
#define NST  3              // pipeline stages

// ---- scratch ----
__device__ float  g_ssrc[NN];
__device__ float  g_sdst[NN];
__device__ __half g_ph[NN];
__device__ __half g_qh[NN];
__device__ __half g_Ah[NN];
__device__ __half g_Bh[NN];
__device__ float  g_V;
__device__ __half g_hT[(size_t)DOUT * NN];
__device__ float  g_part[(size_t)JS * NN * DOUT];
__device__ float  g_denomp[JS * NN];

// ============================ PTX helpers ============================
__device__ __forceinline__ uint32_t smem_u32(const void* p) {
    uint32_t a;
    asm("{ .reg .u64 t; cvta.to.shared.u64 t, %1; cvt.u32.u64 %0, t; }" : "=r"(a) : "l"(p));
    return a;
}
#define LDMX4(r0, r1, r2, r3, a) \
    asm volatile("ldmatrix.sync.aligned.m8n8.x4.shared.b16 {%0,%1,%2,%3}, [%4];" \
                 : "=r"(r0), "=r"(r1), "=r"(r2), "=r"(r3) : "r"(a))
#define MMA16816(c, a0, a1, a2, a3, b0, b1) \
    asm volatile("mma.sync.aligned.m16n8k16.row.col.f32.f16.f16.f32 " \
                 "{%0,%1,%2,%3},{%4,%5,%6,%7},{%8,%9},{%0,%1,%2,%3};" \
                 : "+f"((c)[0]), "+f"((c)[1]), "+f"((c)[2]), "+f"((c)[3]) \
                 : "r"(a0), "r"(a1), "r"(a2), "r"(a3), "r"(b0), "r"(b1))
#define CPASYNC16(dst, src) \
    asm volatile("cp.async.cg.shared.global [%0], [%1], 16;" :: "r"(dst), "l"(src))
#define CP_MBAR_ARRIVE(m) \
    asm volatile("cp.async.mbarrier.arrive.shared.b64 [%0];" :: "r"(m) : "memory")
#define MBARRIER_INIT(addr, cnt) \
    asm volatile("mbarrier.init.shared.b64 [%0], %1;" :: "r"(addr), "r"(cnt) : "memory")
#define MBARRIER_ARRIVE(addr) \
    asm volatile("mbarrier.arrive.shared.b64 _, [%0];" :: "r"(addr) : "memory")
#define MBARRIER_WAIT_PARITY(addr, par) do {                                        \
    uint32_t _m = (addr), _p = (par), _d;                                           \
    asm volatile("{\n\t.reg .pred p;\n\t"                                           \
        "mbarrier.try_wait.parity.acquire.cta.shared::cta.b64 p, [%1], %2;\n\t"     \
        "selp.b32 %0, 1, 0, p;\n\t}" : "=r"(_d) : "r"(_m), "r"(_p) : "memory");     \
    if (!_d) {                                                                       \
        asm volatile("{\n\t.reg .pred P1;\n\t"                                      \
            "W_%=:\n\t"                                                              \
            "mbarrier.try_wait.parity.acquire.cta.shared::cta.b64 P1, [%0], %1, 0x989680;\n\t" \
            "@P1 bra.uni D_%=;\n\tbra.uni W_%=;\n\tD_%=:\n\t}"                      \
            :: "r"(_m), "r"(_p) : "memory");                                        \
    }                                                                                \
} while (0)

// =====================================================================
// k1: h = x@W + bW (fp32); hT fp16 coalesced; s_src = h.a1, s_dst = h.a2
// =====================================================================
__global__ void __launch_bounds__(128) k_linear(
    const float* __restrict__ x, const float* __restrict__ W,
    const float* __restrict__ bW, const float* __restrict__ a1,
    const float* __restrict__ a2)
{
    __shared__ __align__(16) float xs[16][33];
    __shared__ __align__(16) float Ws[16][DOUT];

    const int tid = threadIdx.x;
    const int dg = tid & 15;
    const int rg = tid >> 4;
    const int row0 = blockIdx.x * TI;

    float acc[4][8];
#pragma unroll
    for (int r = 0; r < 4; r++)
#pragma unroll
        for (int c = 0; c < 8; c++) acc[r][c] = 0.f;

    for (int kb = 0; kb < DIN; kb += 16) {
        __syncthreads();
#pragma unroll
        for (int m = 0; m < 4; m++) {
            int i = tid + 128 * m;
            int rr = i >> 4, kk = i & 15;
            xs[kk][rr] = x[(row0 + rr) * DIN + kb + kk];
        }
        const float4* Wg = (const float4*)(W + kb * DOUT);
        float4* Wl = (float4*)Ws;
#pragma unroll
        for (int m = 0; m < 4; m++) Wl[tid + 128 * m] = Wg[tid + 128 * m];
        __syncthreads();

#pragma unroll
        for (int k = 0; k < 16; k++) {
            float a_[4];
#pragma unroll
            for (int r = 0; r < 4; r++) a_[r] = xs[k][rg * 4 + r];
            float4 b0 = *(const float4*)&Ws[k][dg * 8];
            float4 b1 = *(const float4*)&Ws[k][dg * 8 + 4];
            float b_[8] = {b0.x, b0.y, b0.z, b0.w, b1.x, b1.y, b1.z, b1.w};
#pragma unroll
            for (int r = 0; r < 4; r++)
#pragma unroll
                for (int c = 0; c < 8; c++) acc[r][c] = fmaf(a_[r], b_[c], acc[r][c]);
        }
    }

    float4 bv0 = *(const float4*)&bW[dg * 8];
    float4 bv1 = *(const float4*)&bW[dg * 8 + 4];
    float bv[8] = {bv0.x, bv0.y, bv0.z, bv0.w, bv1.x, bv1.y, bv1.z, bv1.w};
    float4 a10 = *(const float4*)&a1[dg * 8];
    float4 a11 = *(const float4*)&a1[dg * 8 + 4];
    float a1v[8] = {a10.x, a10.y, a10.z, a10.w, a11.x, a11.y, a11.z, a11.w};
    float4 a20 = *(const float4*)&a2[dg * 8];
    float4 a21 = *(const float4*)&a2[dg * 8 + 4];
    float a2v[8] = {a20.x, a20.y, a20.z, a20.w, a21.x, a21.y, a21.z, a21.w};

    float s1[4], s2[4];
#pragma unroll
    for (int r = 0; r < 4; r++) {
        s1[r] = 0.f; s2[r] = 0.f;
#pragma unroll
        for (int c = 0; c < 8; c++) {
            acc[r][c] += bv[c];
            s1[r] = fmaf(acc[r][c], a1v[c], s1[r]);
            s2[r] = fmaf(acc[r][c], a2v[c], s2[r]);
        }
    }
#pragma unroll
    for (int c = 0; c < 8; c++) {
        __half2 lo = __floats2half2_rn(acc[0][c], acc[1][c]);
        __half2 hi = __floats2half2_rn(acc[2][c], acc[3][c]);
        uint2 pk = make_uint2(*(uint32_t*)&lo, *(uint32_t*)&hi);
        *(uint2*)(g_hT + (size_t)(dg * 8 + c) * NN + row0 + rg * 4) = pk;
    }
#pragma unroll
    for (int r = 0; r < 4; r++) {
#pragma unroll
        for (int off = 8; off > 0; off >>= 1) {
            s1[r] += __shfl_down_sync(0xffffffffu, s1[r], off, 16);
            s2[r] += __shfl_down_sync(0xffffffffu, s2[r], off, 16);
        }
    }
    if (dg == 0) {
#pragma unroll
        for (int r = 0; r < 4; r++) {
            int row = row0 + rg * 4 + r;
            g_ssrc[row] = s1[r];
            g_sdst[row] = s2[r];
        }
    }
}

// =====================================================================
__global__ void __launch_bounds__(1024) k_vmax()
{
    __shared__ float red[32];
    int tid = threadIdx.x;
    int lane = tid & 31, wid = tid >> 5;
    float vmax = -1e30f;
    for (int j = tid; j < NN; j += 1024) vmax = fmaxf(vmax, g_sdst[j]);
#pragma unroll
    for (int off = 16; off > 0; off >>= 1)
        vmax = fmaxf(vmax, __shfl_down_sync(0xffffffffu, vmax, off));
    if (lane == 0) red[wid] = vmax;
    __syncthreads();
    if (wid == 0) {
        float m = red[lane];
#pragma unroll
        for (int off = 16; off > 0; off >>= 1)
            m = fmaxf(m, __shfl_down_sync(0xffffffffu, m, off));
        if (lane == 0) g_V = m;
    }
}

__global__ void k_prep(const float* __restrict__ ba)
{
    int i = blockIdx.x * blockDim.x + threadIdx.x;
    if (i >= NN) return;
    const float V = g_V;
    float u = g_ssrc[i] + ba[0];
    float t = u + V;
    float c = fmaxf(t, 0.01f * t);
    g_Ah[i] = __float2half(expf(t - c));
    g_Bh[i] = __float2half(expf(0.01f * t - c));
    float v = g_sdst[i] - V;
    g_ph[i] = __float2half(expf(v));
    g_qh[i] = __float2half(expf(0.01f * v));
}

// =====================================================================
// k_main_ws: warp-specialized HMMA masked GEMM.
// 384 thr: warps 0-7 consumers (2m x 4n, 64x128 tile), warps 8-11
// producers (adj -> w gen -> STS; hT cp.async; denom accumulation).
// 3-stage mbarrier ring.
// Full barrier count = 128: one explicit arrive per producer thread
// (orders its STS, release); the per-thread cp.async.mbarrier.arrive
// is self-balancing (+1 at issue, -1 at completion) and gates the
// phase on cp.async landing without consuming a pre-counted arrival.
// =====================================================================
#define WSTB   144
#define STW    (RT * WSTB)              // 9216  (w: 64 x 64 fp16)
#define STH    (DOUT * WSTB)            // 18432 (h: 128 x 64 fp16)
#define STAGE  (STW + STH)              // 27648
#define SM_BAR (NST * STAGE)            // 82944
#define SM_DYN (SM_BAR + 64)

__global__ void __launch_bounds__(384, 2) k_main_ws(const int* __restrict__ adj)
{
    extern __shared__ char smem[];
    const uint32_t sb = smem_u32(smem);

    const int tid  = threadIdx.x;
    const int rt   = blockIdx.x & 127;
    const int seg  = blockIdx.x >> 7;
    const int row0 = rt * RT;
    const int j0   = seg * SEG;

    if (tid == 0) {
#pragma unroll
        for (int s = 0; s < NST; s++) {
            MBARRIER_INIT(sb + SM_BAR + s * 16, 128);       // full (producers)
            MBARRIER_INIT(sb + SM_BAR + s * 16 + 8, 256);   // empty (consumers)
        }
    }
    __syncthreads();

    if (tid >= 256) {
        // ================= PRODUCER =================
        const int ptid = tid - 256;          // 0..127
        const int jq   = ptid & 15;          // j quad: j = jq*4
        const int pg   = ptid >> 4;          // rows pg*8 .. pg*8+7

        __half2 A2[8], B2[8];
#pragma unroll
        for (int k = 0; k < 8; k++) {
            A2[k] = __half2half2(g_Ah[row0 + pg * 8 + k]);
            B2[k] = __half2half2(g_Bh[row0 + pg * 8 + k]);
        }

        int4 adjc[8];
        uint2 pc, qc;
        {
            const int* ap = adj + (size_t)(row0 + pg * 8) * NN + j0 + jq * 4;
#pragma unroll
            for (int k = 0; k < 8; k++) adjc[k] = *(const int4*)(ap + (size_t)k * NN);
            pc = *(const uint2*)&g_ph[j0 + jq * 4];
            qc = *(const uint2*)&g_qh[j0 + jq * 4];
        }

        float2 dacc[8];
#pragma unroll
        for (int k = 0; k < 8; k++) dacc[k] = make_float2(0.f, 0.f);

        int st = 0, phe = 1;
        for (int c = 0; c < NCH; c++) {
            const uint32_t fullb  = sb + SM_BAR + st * 16;
            const uint32_t emptyb = fullb + 8;
            MBARRIER_WAIT_PARITY(emptyb, phe);

            // ---- generate w tile ----
            char* wb = smem + st * STAGE;
            const __half2 p01 = ((const __half2*)&pc)[0];
            const __half2 p23 = ((const __half2*)&pc)[1];
            const __half2 q01 = ((const __half2*)&qc)[0];
            const __half2 q23 = ((const __half2*)&qc)[1];
#pragma unroll
            for (int k = 0; k < 8; k++) {
                uint32_t m01 = (uint32_t)(adjc[k].x | (adjc[k].y << 16)) * 0xFFFFu;
                uint32_t m23 = (uint32_t)(adjc[k].z | (adjc[k].w << 16)) * 0xFFFFu;
                __half2 w01 = __hmax2(__hmul2(A2[k], p01), __hmul2(B2[k], q01));
                __half2 w23 = __hmax2(__hmul2(A2[k], p23), __hmul2(B2[k], q23));
                uint32_t u01 = (*(uint32_t*)&w01) & m01;
                uint32_t u23 = (*(uint32_t*)&w23) & m23;
                *(uint2*)(wb + (pg * 8 + k) * WSTB + jq * 8) = make_uint2(u01, u23);
                float2 f01 = __half22float2(*(__half2*)&u01);
                float2 f23 = __half22float2(*(__half2*)&u23);
                dacc[k].x += f01.x + f23.x;
                dacc[k].y += f01.y + f23.y;
            }

            // ---- hT cp.async: one 128B d-row per thread ----
            {
                const __half* hs = g_hT + (size_t)ptid * NN + j0 + c * KC;
                uint32_t hd = sb + st * STAGE + STW + ptid * WSTB;
#pragma unroll
                for (int i = 0; i < 8; i++) CPASYNC16(hd + i * 16, hs + i * 8);
            }
            CP_MBAR_ARRIVE(fullb);      // +1 at issue, -1 when cp.asyncs land
            MBARRIER_ARRIVE(fullb);     // counted arrive; orders the STS (release)

            // ---- prefetch next chunk (latency hides behind wait) ----
            if (c + 1 < NCH) {
                const int jb1 = j0 + (c + 1) * KC;
                const int* ap = adj + (size_t)(row0 + pg * 8) * NN + jb1 + jq * 4;
#pragma unroll
                for (int k = 0; k < 8; k++) adjc[k] = *(const int4*)(ap + (size_t)k * NN);
                pc = *(const uint2*)&g_ph[jb1 + jq * 4];
                qc = *(const uint2*)&g_qh[jb1 + jq * 4];
            }
            if (++st == NST) { st = 0; phe ^= 1; }
        }

        // ---- denominator: reduce over jq lanes (full 64-j coverage) ----
#pragma unroll
        for (int k = 0; k < 8; k++) {
            float d = dacc[k].x + dacc[k].y;
#pragma unroll
            for (int off = 8; off > 0; off >>= 1)
                d += __shfl_xor_sync(0xffffffffu, d, off);
            if (jq == 0)
                g_denomp[seg * NN + row0 + pg * 8 + k] = d;
        }
    } else {
        // ================= CONSUMER =================
        const int wid = tid >> 5, lane = tid & 31;
        const int wm = wid & 1, wn = wid >> 1;
        const int mi = lane >> 3, r8 = lane & 7;

        float acc[2][4][4];
#pragma unroll
        for (int mt = 0; mt < 2; mt++)
#pragma unroll
            for (int nt = 0; nt < 4; nt++)
#pragma unroll
                for (int k = 0; k < 4; k++) acc[mt][nt][k] = 0.f;

        const uint32_t aoff0 = (wm * 32 + ((mi & 1) ? 8 : 0) + r8) * WSTB
                             + (((mi >> 1) ? 8 : 0)) * 2;
        const uint32_t boff  = STW + (wn * 32 + (mi >> 1) * 8 + r8) * WSTB
                             + (((mi & 1) ? 8 : 0)) * 2;

        int st = 0, phf = 0;
        for (int c = 0; c < NCH; c++) {
            const uint32_t fullb  = sb + SM_BAR + st * 16;
            const uint32_t emptyb = fullb + 8;
            MBARRIER_WAIT_PARITY(fullb, phf);

            const uint32_t base = sb + st * STAGE;
#pragma unroll
            for (int ks = 0; ks < 4; ks++) {
                uint32_t a[2][4];
#pragma unroll
                for (int mt = 0; mt < 2; mt++)
                    LDMX4(a[mt][0], a[mt][1], a[mt][2], a[mt][3],
                          base + aoff0 + mt * 16 * WSTB + ks * 32);
                uint32_t bfr[4][2];
                LDMX4(bfr[0][0], bfr[0][1], bfr[1][0], bfr[1][1],
                      base + boff + ks * 32);
                LDMX4(bfr[2][0], bfr[2][1], bfr[3][0], bfr[3][1],
                      base + boff + 16 * WSTB + ks * 32);
#pragma unroll
                for (int mt = 0; mt < 2; mt++)
#pragma unroll
                    for (int nt = 0; nt < 4; nt++)
                        MMA16816(acc[mt][nt], a[mt][0], a[mt][1], a[mt][2], a[mt][3],
                                 bfr[nt][0], bfr[nt][1]);
            }
            MBARRIER_ARRIVE(emptyb);
            if (++st == NST) { st = 0; phf ^= 1; }
        }

        // ---- epilogue ----
        const int rlo = row0 + wm * 32 + (lane >> 2);
        const int col = wn * 32 + (lane & 3) * 2;
        float* pp = g_part + (size_t)seg * NN * DOUT;
#pragma unroll
        for (int mt = 0; mt < 2; mt++) {
#pragma unroll
            for (int nt = 0; nt < 4; nt++) {
                float2 lo = make_float2(acc[mt][nt][0], acc[mt][nt][1]);
                float2 hi = make_float2(acc[mt][nt][2], acc[mt][nt][3]);
                *(float2*)&pp[(size_t)(rlo + mt * 16) * DOUT + nt * 8 + col] = lo;
                *(float2*)&pp[(size_t)(rlo + mt * 16 + 8) * DOUT + nt * 8 + col] = hi;
            }
        }
    }
}

// =====================================================================
__global__ void __launch_bounds__(256) k_combine(float* __restrict__ out)
{
    const int idx = blockIdx.x * 256 + threadIdx.x;
    const int i  = idx >> 5;
    const int dq = idx & 31;
    float4 s = make_float4(0.f, 0.f, 0.f, 0.f);
    float den = 0.f;
#pragma unroll
    for (int sg = 0; sg < JS; sg++) {
        float4 v = *(const float4*)&g_part[((size_t)sg * NN + i) * DOUT + dq * 4];
        s.x += v.x; s.y += v.y; s.z += v.z; s.w += v.w;
        den += g_denomp[sg * NN + i];
    }
    const float inv = 1.0f / fmaxf(den, 1e-30f);
    s.x *= inv; s.y *= inv; s.z *= inv; s.w *= inv;
    *(float4*)&out[(size_t)i * DOUT + dq * 4] = s;
}

// =====================================================================
extern "C" void kernel_launch(void* const* d_in, const int* in_sizes, int n_in,
                              void* d_out, int out_size)
{
    const float* x   = (const float*)d_in[0];
    const int*   adj = (const int*)  d_in[1];
    const float* W   = (const float*)d_in[2];
    const float* bW  = (const float*)d_in[3];
    const float* a1  = (const float*)d_in[4];
    const float* a2  = (const float*)d_in[5];
    const float* ba  = (const float*)d_in[6];
    float* out = (float*)d_out;

    cudaFuncSetAttribute(k_main_ws, cudaFuncAttributeMaxDynamicSharedMemorySize, SM_DYN);

    k_linear<<<NN / TI, 128>>>(x, W, bW, a1, a2);
    k_vmax<<<1, 1024>>>();
    k_prep<<<NN / 256, 256>>>(ba);
    k_main_ws<<<128 * JS, 384, SM_DYN>>>(adj);
    k_combine<<<NN * 32 / 256, 256>>>(out);
}

// round 8
// speedup vs baseline: 1.1762x; 1.1762x over previous
#include <cuda_runtime.h>
#include <cuda_fp16.h>
#include <math.h>
#include <stdint.h>

#define NN   8192
#define DIN  256
#define DOUT 128
#define TI   16             // rows per block in k_linear
#define JS   8              // j segments
#define SEG  (NN / JS)      // 1024
#define KC   64             // j per chunk
#define NCH  (SEG / KC)     // 16
#define RT   64             // i-rows per CTA tile in k_main

// ---- scratch ----
__device__ float  g_ssrc[NN];
__device__ float  g_sdst[NN];
__device__ __half g_ph[NN];
__device__ __half g_qh[NN];
__device__ __half g_Ah[NN];
__device__ __half g_Bh[NN];
__device__ float  g_V;
__device__ __half g_hT[(size_t)DOUT * NN];   // h transposed, fp16 (2MB)
__device__ float  g_num[(size_t)NN * DOUT];  // 4MB accumulators
__device__ float  g_den[NN];

// ============================ PTX helpers ============================
__device__ __forceinline__ uint32_t smem_u32(const void* p) {
    uint32_t a;
    asm("{ .reg .u64 t; cvta.to.shared.u64 t, %1; cvt.u32.u64 %0, t; }" : "=r"(a) : "l"(p));
    return a;
}
#define LDMX4(r0, r1, r2, r3, a) \
    asm volatile("ldmatrix.sync.aligned.m8n8.x4.shared.b16 {%0,%1,%2,%3}, [%4];" \
                 : "=r"(r0), "=r"(r1), "=r"(r2), "=r"(r3) : "r"(a))
#define MMA16816(c, a0, a1, a2, a3, b0, b1) \
    asm volatile("mma.sync.aligned.m16n8k16.row.col.f32.f16.f16.f32 " \
                 "{%0,%1,%2,%3},{%4,%5,%6,%7},{%8,%9},{%0,%1,%2,%3};" \
                 : "+f"((c)[0]), "+f"((c)[1]), "+f"((c)[2]), "+f"((c)[3]) \
                 : "r"(a0), "r"(a1), "r"(a2), "r"(a3), "r"(b0), "r"(b1))
#define CPASYNC16(dst, src) \
    asm volatile("cp.async.cg.shared.global [%0], [%1], 16;" :: "r"(dst), "l"(src))
#define CPCOMMIT() asm volatile("cp.async.commit_group;" ::: "memory")
#define CPWAIT0()  asm volatile("cp.async.wait_group 0;" ::: "memory")

// =====================================================================
// k1: h = x@W + bW (fp32); hT fp16; s_src = h.a1, s_dst = h.a2
// 128 thr, 16 rows x 128 cols per block, grid 512
// =====================================================================
__global__ void __launch_bounds__(128) k_linear(
    const float* __restrict__ x, const float* __restrict__ W,
    const float* __restrict__ bW, const float* __restrict__ a1,
    const float* __restrict__ a2)
{
    __shared__ __align__(16) float xs[16][17];
    __shared__ __align__(16) float Ws[16][DOUT];

    const int tid = threadIdx.x;
    const int dg = tid & 15;        // col group: cols [8*dg, 8*dg+8)
    const int rg = tid >> 4;        // row group: rows [2*rg, 2*rg+2)
    const int row0 = blockIdx.x * TI;

    float acc[2][8];
#pragma unroll
    for (int r = 0; r < 2; r++)
#pragma unroll
        for (int c = 0; c < 8; c++) acc[r][c] = 0.f;

    for (int kb = 0; kb < DIN; kb += 16) {
        __syncthreads();
#pragma unroll
        for (int m = 0; m < 2; m++) {
            int i = tid + 128 * m;
            int rr = i >> 4, kk = i & 15;
            xs[kk][rr] = x[(row0 + rr) * DIN + kb + kk];
        }
        const float4* Wg = (const float4*)(W + kb * DOUT);
        float4* Wl = (float4*)Ws;
#pragma unroll
        for (int m = 0; m < 4; m++) Wl[tid + 128 * m] = Wg[tid + 128 * m];
        __syncthreads();

#pragma unroll
        for (int k = 0; k < 16; k++) {
            float a0 = xs[k][rg * 2 + 0];
            float a1_ = xs[k][rg * 2 + 1];
            float4 b0 = *(const float4*)&Ws[k][dg * 8];
            float4 b1 = *(const float4*)&Ws[k][dg * 8 + 4];
            float b_[8] = {b0.x, b0.y, b0.z, b0.w, b1.x, b1.y, b1.z, b1.w};
#pragma unroll
            for (int c = 0; c < 8; c++) {
                acc[0][c] = fmaf(a0, b_[c], acc[0][c]);
                acc[1][c] = fmaf(a1_, b_[c], acc[1][c]);
            }
        }
    }

    float4 bv0 = *(const float4*)&bW[dg * 8];
    float4 bv1 = *(const float4*)&bW[dg * 8 + 4];
    float bv[8] = {bv0.x, bv0.y, bv0.z, bv0.w, bv1.x, bv1.y, bv1.z, bv1.w};
    float4 a10 = *(const float4*)&a1[dg * 8];
    float4 a11 = *(const float4*)&a1[dg * 8 + 4];
    float a1v[8] = {a10.x, a10.y, a10.z, a10.w, a11.x, a11.y, a11.z, a11.w};
    float4 a20 = *(const float4*)&a2[dg * 8];
    float4 a21 = *(const float4*)&a2[dg * 8 + 4];
    float a2v[8] = {a20.x, a20.y, a20.z, a20.w, a21.x, a21.y, a21.z, a21.w};

    float s1[2], s2[2];
#pragma unroll
    for (int r = 0; r < 2; r++) {
        s1[r] = 0.f; s2[r] = 0.f;
#pragma unroll
        for (int c = 0; c < 8; c++) {
            acc[r][c] += bv[c];
            s1[r] = fmaf(acc[r][c], a1v[c], s1[r]);
            s2[r] = fmaf(acc[r][c], a2v[c], s2[r]);
        }
    }
#pragma unroll
    for (int c = 0; c < 8; c++) {
        __half2 pk = __floats2half2_rn(acc[0][c], acc[1][c]);
        *(uint32_t*)(g_hT + (size_t)(dg * 8 + c) * NN + row0 + rg * 2) =
            *(uint32_t*)&pk;
    }
#pragma unroll
    for (int r = 0; r < 2; r++) {
#pragma unroll
        for (int off = 8; off > 0; off >>= 1) {
            s1[r] += __shfl_down_sync(0xffffffffu, s1[r], off, 16);
            s2[r] += __shfl_down_sync(0xffffffffu, s2[r], off, 16);
        }
    }
    if (dg == 0) {
#pragma unroll
        for (int r = 0; r < 2; r++) {
            int row = row0 + rg * 2 + r;
            g_ssrc[row] = s1[r];
            g_sdst[row] = s2[r];
        }
    }
}

// =====================================================================
__global__ void __launch_bounds__(1024) k_vmax()
{
    __shared__ float red[32];
    int tid = threadIdx.x;
    int lane = tid & 31, wid = tid >> 5;
    float vmax = -1e30f;
    for (int j = tid; j < NN; j += 1024) vmax = fmaxf(vmax, g_sdst[j]);
#pragma unroll
    for (int off = 16; off > 0; off >>= 1)
        vmax = fmaxf(vmax, __shfl_down_sync(0xffffffffu, vmax, off));
    if (lane == 0) red[wid] = vmax;
    __syncthreads();
    if (wid == 0) {
        float m = red[lane];
#pragma unroll
        for (int off = 16; off > 0; off >>= 1)
            m = fmaxf(m, __shfl_down_sync(0xffffffffu, m, off));
        if (lane == 0) g_V = m;
    }
}

__global__ void k_prep(const float* __restrict__ ba)
{
    int i = blockIdx.x * blockDim.x + threadIdx.x;
    if (i >= NN) return;
    const float V = g_V;
    float u = g_ssrc[i] + ba[0];
    float t = u + V;
    float c = fmaxf(t, 0.01f * t);
    g_Ah[i] = __float2half(expf(t - c));
    g_Bh[i] = __float2half(expf(0.01f * t - c));
    float v = g_sdst[i] - V;
    g_ph[i] = __float2half(expf(v));
    g_qh[i] = __float2half(expf(0.01f * v));
}

// =====================================================================
__global__ void __launch_bounds__(256) k_zero()
{
    int i = blockIdx.x * 256 + threadIdx.x;      // grid covers NN*DOUT
    g_num[i] = 0.f;
    if (i < NN) g_den[i] = 0.f;
}

// =====================================================================
// k_main_m: fused HMMA masked GEMM (R4 structure). CTA = 256 thr
// (8 warps, 2m x 4n), 64 i-rows x 128 d over a 1024-j segment in
// 64-j chunks. Epilogue: RED-atomic accumulation into g_num/g_den.
// =====================================================================
#define WSTB   144
#define SM_W0  0
#define SM_W1  (RT * WSTB)              // 9216
#define SM_H0  (2 * RT * WSTB)          // 18432
#define SM_H1  (SM_H0 + 128 * WSTB)     // 36864
#define SM_AS  (SM_H1 + 128 * WSTB)     // 55296
#define SM_BS  (SM_AS + 128)
#define SM_DYN (SM_BS + 128 + 256)

__global__ void __launch_bounds__(256, 3) k_main_m(const int* __restrict__ adj)
{
    extern __shared__ char smem[];
    const uint32_t sb = smem_u32(smem);
    __half* As = (__half*)(smem + SM_AS);
    __half* Bs = (__half*)(smem + SM_BS);

    const int tid  = threadIdx.x;
    const int wid  = tid >> 5, lane = tid & 31;
    const int rt   = blockIdx.x & 127;
    const int seg  = blockIdx.x >> 7;
    const int row0 = rt * RT;
    const int j0   = seg * SEG;

    const int jp  = tid & 31;          // j pair (j = jp*2, jp*2+1)
    const int grp = tid >> 5;          // rows grp*8 .. grp*8+7
    const int dd  = tid >> 1, qq = tid & 1;   // hT copy: 64B per thread
    const int wm  = wid & 1, wn = wid >> 1;

    if (tid < RT) { As[tid] = g_Ah[row0 + tid]; Bs[tid] = g_Bh[row0 + tid]; }

    float acc[2][4][4];
#pragma unroll
    for (int mt = 0; mt < 2; mt++)
#pragma unroll
        for (int nt = 0; nt < 4; nt++)
#pragma unroll
            for (int k = 0; k < 4; k++) acc[mt][nt][k] = 0.f;
    float dacc[2][4] = {{0.f,0.f,0.f,0.f},{0.f,0.f,0.f,0.f}};
    const uint32_t ones = 0x3C003C00u;

    // ---- prologue: stage h[0], prefetch adj[0], p/q[0] ----
    int2 adjv[8];
    uint32_t p2r, q2r;
    {
        const __half* hs = g_hT + (size_t)dd * NN + j0 + qq * 32;
        uint32_t hd = sb + SM_H0 + dd * WSTB + qq * 64;
#pragma unroll
        for (int k = 0; k < 4; k++) CPASYNC16(hd + 16 * k, hs + 8 * k);
        CPCOMMIT();
        const int* ap = adj + (size_t)(row0 + grp * 8) * NN + j0 + jp * 2;
#pragma unroll
        for (int k = 0; k < 8; k++) adjv[k] = *(const int2*)(ap + (size_t)k * NN);
        p2r = *(const uint32_t*)&g_ph[j0 + jp * 2];
        q2r = *(const uint32_t*)&g_qh[j0 + jp * 2];
    }
    __syncthreads();   // As/Bs visible

    for (int c = 0; c < NCH; c++) {
        const int b = c & 1;
        const uint32_t wb = sb + (b ? SM_W1 : SM_W0);
        const uint32_t hb = sb + (b ? SM_H1 : SM_H0);

        // ---- generate w tile (half2 + mask-multiply) ----
        {
            const __half2 p2 = *(__half2*)&p2r;
            const __half2 q2 = *(__half2*)&q2r;
#pragma unroll
            for (int k = 0; k < 8; k++) {
                const int i = grp * 8 + k;
                __half2 A2 = __half2half2(As[i]);
                __half2 B2 = __half2half2(Bs[i]);
                uint32_t m = (uint32_t)(adjv[k].x | (adjv[k].y << 16)) * 0xFFFFu;
                __half2 w = __hmax2(__hmul2(A2, p2), __hmul2(B2, q2));
                *(uint32_t*)(smem + (b ? SM_W1 : SM_W0) + i * WSTB + jp * 4) =
                    (*(uint32_t*)&w) & m;
            }
        }
        CPWAIT0();
        __syncthreads();

        // ---- prefetch chunk c+1 ----
        if (c + 1 < NCH) {
            const int jb1 = j0 + (c + 1) * KC;
            const __half* hs = g_hT + (size_t)dd * NN + jb1 + qq * 32;
            uint32_t hd = sb + (b ? SM_H0 : SM_H1) + dd * WSTB + qq * 64;
#pragma unroll
            for (int k = 0; k < 4; k++) CPASYNC16(hd + 16 * k, hs + 8 * k);
            CPCOMMIT();
            const int* ap = adj + (size_t)(row0 + grp * 8) * NN + jb1 + jp * 2;
#pragma unroll
            for (int k = 0; k < 8; k++) adjv[k] = *(const int2*)(ap + (size_t)k * NN);
            p2r = *(const uint32_t*)&g_ph[jb1 + jp * 2];
            q2r = *(const uint32_t*)&g_qh[jb1 + jp * 2];
        }

        // ---- MMA: 4 k-steps ----
        const int mi = lane >> 3, r8 = lane & 7;
#pragma unroll
        for (int ks = 0; ks < 4; ks++) {
            uint32_t a[2][4];
#pragma unroll
            for (int mt = 0; mt < 2; mt++) {
                int arow = wm * 32 + mt * 16 + ((mi & 1) ? 8 : 0) + r8;
                int acol = ks * 16 + ((mi >> 1) ? 8 : 0);
                LDMX4(a[mt][0], a[mt][1], a[mt][2], a[mt][3],
                      wb + arow * WSTB + acol * 2);
            }
            uint32_t bfr[4][2];
            {
                int nrow = wn * 32 + (mi >> 1) * 8 + r8;
                int bcol = ks * 16 + ((mi & 1) ? 8 : 0);
                LDMX4(bfr[0][0], bfr[0][1], bfr[1][0], bfr[1][1],
                      hb + nrow * WSTB + bcol * 2);
                LDMX4(bfr[2][0], bfr[2][1], bfr[3][0], bfr[3][1],
                      hb + (nrow + 16) * WSTB + bcol * 2);
            }
#pragma unroll
            for (int mt = 0; mt < 2; mt++)
#pragma unroll
                for (int nt = 0; nt < 4; nt++)
                    MMA16816(acc[mt][nt], a[mt][0], a[mt][1], a[mt][2], a[mt][3],
                             bfr[nt][0], bfr[nt][1]);
            if (wn == 0) {
#pragma unroll
                for (int mt = 0; mt < 2; mt++)
                    MMA16816(dacc[mt], a[mt][0], a[mt][1], a[mt][2], a[mt][3],
                             ones, ones);
            }
        }
    }

    // ---- epilogue: RED-atomic accumulation ----
    const int rlo = row0 + wm * 32 + (lane >> 2);
    const int col = wn * 32 + (lane & 3) * 2;
#pragma unroll
    for (int mt = 0; mt < 2; mt++) {
#pragma unroll
        for (int nt = 0; nt < 4; nt++) {
            float* p0 = &g_num[(size_t)(rlo + mt * 16) * DOUT + nt * 8 + col];
            float* p1 = &g_num[(size_t)(rlo + mt * 16 + 8) * DOUT + nt * 8 + col];
            atomicAdd(p0,     acc[mt][nt][0]);
            atomicAdd(p0 + 1, acc[mt][nt][1]);
            atomicAdd(p1,     acc[mt][nt][2]);
            atomicAdd(p1 + 1, acc[mt][nt][3]);
        }
    }
    if (wn == 0 && (lane & 3) == 0) {
#pragma unroll
        for (int mt = 0; mt < 2; mt++) {
            atomicAdd(&g_den[rlo + mt * 16],     dacc[mt][0]);
            atomicAdd(&g_den[rlo + mt * 16 + 8], dacc[mt][2]);
        }
    }
}

// =====================================================================
__global__ void __launch_bounds__(256) k_combine(float* __restrict__ out)
{
    const int idx = blockIdx.x * 256 + threadIdx.x;   // NN*DOUT/4 threads
    const int i  = idx >> 5;
    const int dq = idx & 31;
    float4 v = *(const float4*)&g_num[(size_t)i * DOUT + dq * 4];
    const float inv = 1.0f / fmaxf(g_den[i], 1e-30f);
    v.x *= inv; v.y *= inv; v.z *= inv; v.w *= inv;
    *(float4*)&out[(size_t)i * DOUT + dq * 4] = v;
}

// =====================================================================
extern "C" void kernel_launch(void* const* d_in, const int* in_sizes, int n_in,
                              void* d_out, int out_size)
{
    const float* x   = (const float*)d_in[0];
    const int*   adj = (const int*)  d_in[1];
    const float* W   = (const float*)d_in[2];
    const float* bW  = (const float*)d_in[3];
    const float* a1  = (const float*)d_in[4];
    const float* a2  = (const float*)d_in[5];
    const float* ba  = (const float*)d_in[6];
    float* out = (float*)d_out;

    cudaFuncSetAttribute(k_main_m, cudaFuncAttributeMaxDynamicSharedMemorySize, SM_DYN);

    k_zero<<<NN * DOUT / 256, 256>>>();
    k_linear<<<NN / TI, 128>>>(x, W, bW, a1, a2);
    k_vmax<<<1, 1024>>>();
    k_prep<<<NN / 256, 256>>>(ba);
    k_main_m<<<128 * JS, 256, SM_DYN>>>(adj);
    k_combine<<<NN * DOUT / 4 / 256, 256>>>(out);
}

// round 9
// speedup vs baseline: 1.4569x; 1.2387x over previous
#include <cuda_runtime.h>
#include <cuda_fp16.h>
#include <math.h>
#include <stdint.h>

#define NN   8192
#define DIN  256
#define DOUT 128
#define JS   8              // j segments
#define SEG  (NN / JS)      // 1024
#define KC   64             // j per chunk
#define NCH  (SEG / KC)     // 16
#define RT   64             // i-rows per CTA tile in k_main

// ---- scratch (zero-initialized at module load; k_combine restores) ----
__device__ float    g_ssrc[NN];
__device__ float    g_sdst[NN];
__device__ __half   g_ph[NN];
__device__ __half   g_qh[NN];
__device__ __half   g_Ah[NN];
__device__ __half   g_Bh[NN];
__device__ unsigned g_Vu;                      // monotone-encoded max(s_dst)
__device__ __half   g_WTh[DOUT * DIN];         // W transposed fp16 [d][k]
__device__ __half   g_hT[(size_t)DOUT * NN];   // h transposed fp16 (2MB)
__device__ float    g_num[(size_t)NN * DOUT];  // 4MB accumulators
__device__ float    g_den[NN];

// ============================ PTX helpers ============================
__device__ __forceinline__ uint32_t smem_u32(const void* p) {
    uint32_t a;
    asm("{ .reg .u64 t; cvta.to.shared.u64 t, %1; cvt.u32.u64 %0, t; }" : "=r"(a) : "l"(p));
    return a;
}
#define LDMX4(r0, r1, r2, r3, a) \
    asm volatile("ldmatrix.sync.aligned.m8n8.x4.shared.b16 {%0,%1,%2,%3}, [%4];" \
                 : "=r"(r0), "=r"(r1), "=r"(r2), "=r"(r3) : "r"(a))
#define MMA16816(c, a0, a1, a2, a3, b0, b1) \
    asm volatile("mma.sync.aligned.m16n8k16.row.col.f32.f16.f16.f32 " \
                 "{%0,%1,%2,%3},{%4,%5,%6,%7},{%8,%9},{%0,%1,%2,%3};" \
                 : "+f"((c)[0]), "+f"((c)[1]), "+f"((c)[2]), "+f"((c)[3]) \
                 : "r"(a0), "r"(a1), "r"(a2), "r"(a3), "r"(b0), "r"(b1))
#define CPASYNC16(dst, src) \
    asm volatile("cp.async.cg.shared.global [%0], [%1], 16;" :: "r"(dst), "l"(src))
#define CPCOMMIT() asm volatile("cp.async.commit_group;" ::: "memory")
#define CPWAIT0()  asm volatile("cp.async.wait_group 0;" ::: "memory")

__device__ __forceinline__ unsigned fenc(float f) {   // monotone float->uint
    int b = __float_as_int(f);
    return (b >= 0) ? ((unsigned)b | 0x80000000u) : ~(unsigned)b;
}
__device__ __forceinline__ float fdec(unsigned k) {
    int b = (k & 0x80000000u) ? (int)(k ^ 0x80000000u) : (int)~k;
    return __int_as_float(b);
}

// =====================================================================
// k_cvtW: W[k][d] fp32 -> g_WTh[d][k] fp16. 32 blocks x 256.
// =====================================================================
__global__ void __launch_bounds__(256) k_cvtW(const float* __restrict__ W)
{
    int gid = blockIdx.x * 256 + threadIdx.x;   // 8192 threads, 4 elems each
    int k  = gid >> 5;
    int d4 = (gid & 31) * 4;
    float4 v = *(const float4*)&W[k * DOUT + d4];
    g_WTh[(d4 + 0) * DIN + k] = __float2half(v.x);
    g_WTh[(d4 + 1) * DIN + k] = __float2half(v.y);
    g_WTh[(d4 + 2) * DIN + k] = __float2half(v.z);
    g_WTh[(d4 + 3) * DIN + k] = __float2half(v.w);
}

// =====================================================================
// k_linear_h: HMMA x@W + bW. CTA = 256 thr (8 warps 2m x 4n), tile
// 64 i x 128 d, K=256 staged once. Epilogue: s1/s2 dots, hT store,
// block-max(s2) -> atomicMax(g_Vu).
// =====================================================================
#define LXS    0                       // x tile: 64 x 528B (256 k fp16 + 16 pad)
#define LWT    33792                   // WT tile: 128 x 528B
#define LHS    0                       // hs reuses xs region: 128 x 144B
#define LSRED  101376                  // float[64][8]
#define LSMAX  103424                  // float[2]
#define LDYN   103440

__global__ void __launch_bounds__(256) k_linear_h(
    const float* __restrict__ x, const float* __restrict__ bW,
    const float* __restrict__ a1, const float* __restrict__ a2)
{
    extern __shared__ char smem[];
    const uint32_t sb = smem_u32(smem);

    const int tid = threadIdx.x;
    const int wid = tid >> 5, lane = tid & 31;
    const int wm = wid & 1, wn = wid >> 1;
    const int row0 = blockIdx.x * 64;

    // ---- stage x (fp32 -> fp16 smem), full 64 x 256 ----
#pragma unroll
    for (int m = 0; m < 32; m++) {
        int idx = tid + 256 * m;
        int r = idx >> 7, kk2 = idx & 127;
        float2 v = *(const float2*)&x[(size_t)(row0 + r) * DIN + kk2 * 2];
        __half2 h2 = __floats2half2_rn(v.x, v.y);
        *(uint32_t*)(smem + LXS + r * 528 + kk2 * 4) = *(uint32_t*)&h2;
    }
    // ---- stage WT via cp.async, full 128 x 256 ----
    {
        const int dd = tid >> 1, qq = tid & 1;
        const __half* src = g_WTh + dd * DIN + qq * 128;
        uint32_t dst = sb + LWT + dd * 528 + qq * 256;
#pragma unroll
        for (int i = 0; i < 16; i++) CPASYNC16(dst + i * 16, src + i * 8);
        CPCOMMIT();
    }
    CPWAIT0();
    __syncthreads();

    float acc[2][4][4];
#pragma unroll
    for (int mt = 0; mt < 2; mt++)
#pragma unroll
        for (int nt = 0; nt < 4; nt++)
#pragma unroll
            for (int k = 0; k < 4; k++) acc[mt][nt][k] = 0.f;

    const int mi = lane >> 3, r8 = lane & 7;
#pragma unroll
    for (int ks = 0; ks < 16; ks++) {
        uint32_t a[2][4];
#pragma unroll
        for (int mt = 0; mt < 2; mt++) {
            int arow = wm * 32 + mt * 16 + ((mi & 1) ? 8 : 0) + r8;
            int acol = ks * 16 + ((mi >> 1) ? 8 : 0);
            LDMX4(a[mt][0], a[mt][1], a[mt][2], a[mt][3],
                  sb + LXS + arow * 528 + acol * 2);
        }
        uint32_t bfr[4][2];
        {
            int nrow = wn * 32 + (mi >> 1) * 8 + r8;
            int bcol = ks * 16 + ((mi & 1) ? 8 : 0);
            LDMX4(bfr[0][0], bfr[0][1], bfr[1][0], bfr[1][1],
                  sb + LWT + nrow * 528 + bcol * 2);
            LDMX4(bfr[2][0], bfr[2][1], bfr[3][0], bfr[3][1],
                  sb + LWT + (nrow + 16) * 528 + bcol * 2);
        }
#pragma unroll
        for (int mt = 0; mt < 2; mt++)
#pragma unroll
            for (int nt = 0; nt < 4; nt++)
                MMA16816(acc[mt][nt], a[mt][0], a[mt][1], a[mt][2], a[mt][3],
                         bfr[nt][0], bfr[nt][1]);
    }
    __syncthreads();   // xs dead; reuse for hs

    // ---- epilogue: bias, s1/s2 partials, hs (transposed) STS ----
    float* sred = (float*)(smem + LSRED);
    float s1p[4] = {0.f, 0.f, 0.f, 0.f};
    float s2p[4] = {0.f, 0.f, 0.f, 0.f};
    const int ra0 = wm * 32 + (lane >> 2);
#pragma unroll
    for (int mt = 0; mt < 2; mt++) {
        const int r_a = ra0 + mt * 16, r_b = r_a + 8;
#pragma unroll
        for (int nt = 0; nt < 4; nt++) {
            const int c0 = wn * 32 + nt * 8 + (lane & 3) * 2;
            float2 bw2 = *(const float2*)&bW[c0];
            float2 a12 = *(const float2*)&a1[c0];
            float2 a22 = *(const float2*)&a2[c0];
            float h0 = acc[mt][nt][0] + bw2.x, h1 = acc[mt][nt][1] + bw2.y;
            float h2 = acc[mt][nt][2] + bw2.x, h3 = acc[mt][nt][3] + bw2.y;
            s1p[mt * 2 + 0] += h0 * a12.x + h1 * a12.y;
            s2p[mt * 2 + 0] += h0 * a22.x + h1 * a22.y;
            s1p[mt * 2 + 1] += h2 * a12.x + h3 * a12.y;
            s2p[mt * 2 + 1] += h2 * a22.x + h3 * a22.y;
            *(__half*)(smem + LHS + (c0    ) * 144 + r_a * 2) = __float2half(h0);
            *(__half*)(smem + LHS + (c0 + 1) * 144 + r_a * 2) = __float2half(h1);
            *(__half*)(smem + LHS + (c0    ) * 144 + r_b * 2) = __float2half(h2);
            *(__half*)(smem + LHS + (c0 + 1) * 144 + r_b * 2) = __float2half(h3);
        }
    }
#pragma unroll
    for (int t = 0; t < 4; t++) {
        s1p[t] += __shfl_xor_sync(0xffffffffu, s1p[t], 1);
        s1p[t] += __shfl_xor_sync(0xffffffffu, s1p[t], 2);
        s2p[t] += __shfl_xor_sync(0xffffffffu, s2p[t], 1);
        s2p[t] += __shfl_xor_sync(0xffffffffu, s2p[t], 2);
    }
    if ((lane & 3) == 0) {
#pragma unroll
        for (int mt = 0; mt < 2; mt++) {
            const int r_a = ra0 + mt * 16, r_b = r_a + 8;
            sred[r_a * 8 + wn]     = s1p[mt * 2 + 0];
            sred[r_a * 8 + 4 + wn] = s2p[mt * 2 + 0];
            sred[r_b * 8 + wn]     = s1p[mt * 2 + 1];
            sred[r_b * 8 + 4 + wn] = s2p[mt * 2 + 1];
        }
    }
    __syncthreads();

    // hT coalesced store from hs
    {
        const int dd = tid >> 1, qq = tid & 1;
        const char* src = smem + LHS + dd * 144 + qq * 64;
        __half* dst = g_hT + (size_t)dd * NN + row0 + qq * 32;
#pragma unroll
        for (int i = 0; i < 4; i++)
            *(uint4*)(dst + i * 8) = *(const uint4*)(src + i * 16);
    }
    // final s reduction + global max
    if (tid < 64) {
        float S1 = sred[tid * 8 + 0] + sred[tid * 8 + 1] + sred[tid * 8 + 2] + sred[tid * 8 + 3];
        float S2 = sred[tid * 8 + 4] + sred[tid * 8 + 5] + sred[tid * 8 + 6] + sred[tid * 8 + 7];
        g_ssrc[row0 + tid] = S1;
        g_sdst[row0 + tid] = S2;
        float mx = S2;
#pragma unroll
        for (int off = 16; off > 0; off >>= 1)
            mx = fmaxf(mx, __shfl_xor_sync(0xffffffffu, mx, off));
        if (lane == 0) ((float*)(smem + LSMAX))[tid >> 5] = mx;
    }
    __syncthreads();
    if (tid == 0) {
        float m = fmaxf(((float*)(smem + LSMAX))[0], ((float*)(smem + LSMAX))[1]);
        atomicMax(&g_Vu, fenc(m));
    }
}

// =====================================================================
__global__ void k_prep(const float* __restrict__ ba)
{
    int i = blockIdx.x * blockDim.x + threadIdx.x;
    if (i >= NN) return;
    const float V = fdec(g_Vu);
    float u = g_ssrc[i] + ba[0];
    float t = u + V;
    float c = fmaxf(t, 0.01f * t);
    g_Ah[i] = __float2half(expf(t - c));
    g_Bh[i] = __float2half(expf(0.01f * t - c));
    float v = g_sdst[i] - V;
    g_ph[i] = __float2half(expf(v));
    g_qh[i] = __float2half(expf(0.01f * v));
}

// =====================================================================
// k_main_m: fused HMMA masked GEMM. CTA = 256 thr (8 warps 2m x 4n),
// 64 i x 128 d over a 1024-j segment in 64-j chunks; atomic epilogue.
// Denominator ones-MMA split across wn==0 (ks 0,1) and wn==1 (ks 2,3).
// =====================================================================
#define WSTB   144
#define SM_W0  0
#define SM_W1  (RT * WSTB)              // 9216
#define SM_H0  (2 * RT * WSTB)          // 18432
#define SM_H1  (SM_H0 + 128 * WSTB)     // 36864
#define SM_AS  (SM_H1 + 128 * WSTB)     // 55296
#define SM_BS  (SM_AS + 128)
#define SM_DYN (SM_BS + 128 + 256)

__global__ void __launch_bounds__(256, 3) k_main_m(const int* __restrict__ adj)
{
    extern __shared__ char smem[];
    const uint32_t sb = smem_u32(smem);
    __half* As = (__half*)(smem + SM_AS);
    __half* Bs = (__half*)(smem + SM_BS);

    const int tid  = threadIdx.x;
    const int wid  = tid >> 5, lane = tid & 31;
    const int rt   = blockIdx.x & 127;
    const int seg  = blockIdx.x >> 7;
    const int row0 = rt * RT;
    const int j0   = seg * SEG;

    const int jp  = tid & 31;
    const int grp = tid >> 5;
    const int dd  = tid >> 1, qq = tid & 1;
    const int wm  = wid & 1, wn = wid >> 1;

    if (tid < RT) { As[tid] = g_Ah[row0 + tid]; Bs[tid] = g_Bh[row0 + tid]; }

    float acc[2][4][4];
#pragma unroll
    for (int mt = 0; mt < 2; mt++)
#pragma unroll
        for (int nt = 0; nt < 4; nt++)
#pragma unroll
            for (int k = 0; k < 4; k++) acc[mt][nt][k] = 0.f;
    float dacc[2][4] = {{0.f,0.f,0.f,0.f},{0.f,0.f,0.f,0.f}};
    const uint32_t ones = 0x3C003C00u;

    int2 adjv[8];
    uint32_t p2r, q2r;
    {
        const __half* hs = g_hT + (size_t)dd * NN + j0 + qq * 32;
        uint32_t hd = sb + SM_H0 + dd * WSTB + qq * 64;
#pragma unroll
        for (int k = 0; k < 4; k++) CPASYNC16(hd + 16 * k, hs + 8 * k);
        CPCOMMIT();
        const int* ap = adj + (size_t)(row0 + grp * 8) * NN + j0 + jp * 2;
#pragma unroll
        for (int k = 0; k < 8; k++) adjv[k] = *(const int2*)(ap + (size_t)k * NN);
        p2r = *(const uint32_t*)&g_ph[j0 + jp * 2];
        q2r = *(const uint32_t*)&g_qh[j0 + jp * 2];
    }
    __syncthreads();

    for (int c = 0; c < NCH; c++) {
        const int b = c & 1;
        const uint32_t wb = sb + (b ? SM_W1 : SM_W0);
        const uint32_t hb = sb + (b ? SM_H1 : SM_H0);

        {
            const __half2 p2 = *(__half2*)&p2r;
            const __half2 q2 = *(__half2*)&q2r;
#pragma unroll
            for (int k = 0; k < 8; k++) {
                const int i = grp * 8 + k;
                __half2 A2 = __half2half2(As[i]);
                __half2 B2 = __half2half2(Bs[i]);
                uint32_t m = (uint32_t)(adjv[k].x | (adjv[k].y << 16)) * 0xFFFFu;
                __half2 w = __hmax2(__hmul2(A2, p2), __hmul2(B2, q2));
                *(uint32_t*)(smem + (b ? SM_W1 : SM_W0) + i * WSTB + jp * 4) =
                    (*(uint32_t*)&w) & m;
            }
        }
        CPWAIT0();
        __syncthreads();

        if (c + 1 < NCH) {
            const int jb1 = j0 + (c + 1) * KC;
            const __half* hs = g_hT + (size_t)dd * NN + jb1 + qq * 32;
            uint32_t hd = sb + (b ? SM_H0 : SM_H1) + dd * WSTB + qq * 64;
#pragma unroll
            for (int k = 0; k < 4; k++) CPASYNC16(hd + 16 * k, hs + 8 * k);
            CPCOMMIT();
            const int* ap = adj + (size_t)(row0 + grp * 8) * NN + jb1 + jp * 2;
#pragma unroll
            for (int k = 0; k < 8; k++) adjv[k] = *(const int2*)(ap + (size_t)k * NN);
            p2r = *(const uint32_t*)&g_ph[jb1 + jp * 2];
            q2r = *(const uint32_t*)&g_qh[jb1 + jp * 2];
        }

        const int mi = lane >> 3, r8 = lane & 7;
#pragma unroll
        for (int ks = 0; ks < 4; ks++) {
            uint32_t a[2][4];
#pragma unroll
            for (int mt = 0; mt < 2; mt++) {
                int arow = wm * 32 + mt * 16 + ((mi & 1) ? 8 : 0) + r8;
                int acol = ks * 16 + ((mi >> 1) ? 8 : 0);
                LDMX4(a[mt][0], a[mt][1], a[mt][2], a[mt][3],
                      wb + arow * WSTB + acol * 2);
            }
            uint32_t bfr[4][2];
            {
                int nrow = wn * 32 + (mi >> 1) * 8 + r8;
                int bcol = ks * 16 + ((mi & 1) ? 8 : 0);
                LDMX4(bfr[0][0], bfr[0][1], bfr[1][0], bfr[1][1],
                      hb + nrow * WSTB + bcol * 2);
                LDMX4(bfr[2][0], bfr[2][1], bfr[3][0], bfr[3][1],
                      hb + (nrow + 16) * WSTB + bcol * 2);
            }
#pragma unroll
            for (int mt = 0; mt < 2; mt++)
#pragma unroll
                for (int nt = 0; nt < 4; nt++)
                    MMA16816(acc[mt][nt], a[mt][0], a[mt][1], a[mt][2], a[mt][3],
                             bfr[nt][0], bfr[nt][1]);
            if ((wn == 0 && ks < 2) || (wn == 1 && ks >= 2)) {
#pragma unroll
                for (int mt = 0; mt < 2; mt++)
                    MMA16816(dacc[mt], a[mt][0], a[mt][1], a[mt][2], a[mt][3],
                             ones, ones);
            }
        }
    }

    // ---- epilogue: atomic accumulation ----
    const int rlo = row0 + wm * 32 + (lane >> 2);
    const int col = wn * 32 + (lane & 3) * 2;
#pragma unroll
    for (int mt = 0; mt < 2; mt++) {
#pragma unroll
        for (int nt = 0; nt < 4; nt++) {
            float* p0 = &g_num[(size_t)(rlo + mt * 16) * DOUT + nt * 8 + col];
            float* p1 = &g_num[(size_t)(rlo + mt * 16 + 8) * DOUT + nt * 8 + col];
            atomicAdd(p0,     acc[mt][nt][0]);
            atomicAdd(p0 + 1, acc[mt][nt][1]);
            atomicAdd(p1,     acc[mt][nt][2]);
            atomicAdd(p1 + 1, acc[mt][nt][3]);
        }
    }
    if (wn < 2 && (lane & 3) == 0) {
#pragma unroll
        for (int mt = 0; mt < 2; mt++) {
            atomicAdd(&g_den[rlo + mt * 16],     dacc[mt][0]);
            atomicAdd(&g_den[rlo + mt * 16 + 8], dacc[mt][2]);
        }
    }
}

// =====================================================================
// k_combine: out = num/den, then restore scratch to zero (determinism
// across graph replays; arrays start zeroed at module load).
// =====================================================================
__global__ void __launch_bounds__(256) k_combine(float* __restrict__ out)
{
    const int idx = blockIdx.x * 256 + threadIdx.x;
    const int i  = idx >> 5;
    const int dq = idx & 31;
    float4 v = *(const float4*)&g_num[(size_t)i * DOUT + dq * 4];
    float den = g_den[i];
    __syncwarp();
    if (dq == 0) g_den[i] = 0.f;
    *(float4*)&g_num[(size_t)i * DOUT + dq * 4] = make_float4(0.f, 0.f, 0.f, 0.f);
    const float inv = 1.0f / fmaxf(den, 1e-30f);
    v.x *= inv; v.y *= inv; v.z *= inv; v.w *= inv;
    *(float4*)&out[(size_t)i * DOUT + dq * 4] = v;
    if (idx == 0) g_Vu = 0u;
}

// =====================================================================
extern "C" void kernel_launch(void* const* d_in, const int* in_sizes, int n_in,
                              void* d_out, int out_size)
{
    const float* x   = (const float*)d_in[0];
    const int*   adj = (const int*)  d_in[1];
    const float* W   = (const float*)d_in[2];
    const float* bW  = (const float*)d_in[3];
    const float* a1  = (const float*)d_in[4];
    const float* a2  = (const float*)d_in[5];
    const float* ba  = (const float*)d_in[6];
    float* out = (float*)d_out;

    cudaFuncSetAttribute(k_linear_h, cudaFuncAttributeMaxDynamicSharedMemorySize, LDYN);
    cudaFuncSetAttribute(k_main_m, cudaFuncAttributeMaxDynamicSharedMemorySize, SM_DYN);

    k_cvtW<<<32, 256>>>(W);
    k_linear_h<<<NN / 64, 256, LDYN>>>(x, bW, a1, a2);
    k_prep<<<NN / 256, 256>>>(ba);
    k_main_m<<<128 * JS, 256, SM_DYN>>>(adj);
    k_combine<<<NN * DOUT / 4 / 256, 256>>>(out);
}

// round 12
// speedup vs baseline: 1.5721x; 1.0791x over previous
#include <cuda_runtime.h>
#include <cuda_fp16.h>
#include <math.h>
#include <stdint.h>

#define NN   8192
#define DIN  256
#define DOUT 128
#define JS   8              // j segments
#define SEG  (NN / JS)      // 1024
#define KC   64             // j per chunk
#define NCH  (SEG / KC)     // 16
#define RT   64             // i-rows per CTA tile in k_main

// ---- scratch (zero-initialized at module load; k_combine restores) ----
__device__ float    g_ssrc[NN];
__device__ float    g_sdst[NN];
__device__ __half   g_ph[NN];
__device__ __half   g_qh[NN];
__device__ __half   g_Ah[NN];
__device__ __half   g_Bh[NN];
__device__ unsigned g_Vu;                      // monotone-encoded max(s_dst)
__device__ __half   g_WTh[DOUT * DIN];         // W transposed fp16 [d][k]
__device__ __half   g_hT[(size_t)DOUT * NN];   // h transposed fp16 (2MB)
__device__ float    g_num[(size_t)NN * DOUT];  // 4MB accumulators
__device__ float    g_den[NN];

// ============================ PTX helpers ============================
__device__ __forceinline__ uint32_t smem_u32(const void* p) {
    uint32_t a;
    asm("{ .reg .u64 t; cvta.to.shared.u64 t, %1; cvt.u32.u64 %0, t; }" : "=r"(a) : "l"(p));
    return a;
}
#define LDMX4(r0, r1, r2, r3, a) \
    asm volatile("ldmatrix.sync.aligned.m8n8.x4.shared.b16 {%0,%1,%2,%3}, [%4];" \
                 : "=r"(r0), "=r"(r1), "=r"(r2), "=r"(r3) : "r"(a))
#define MMA16816(c, a0, a1, a2, a3, b0, b1) \
    asm volatile("mma.sync.aligned.m16n8k16.row.col.f32.f16.f16.f32 " \
                 "{%0,%1,%2,%3},{%4,%5,%6,%7},{%8,%9},{%0,%1,%2,%3};" \
                 : "+f"((c)[0]), "+f"((c)[1]), "+f"((c)[2]), "+f"((c)[3]) \
                 : "r"(a0), "r"(a1), "r"(a2), "r"(a3), "r"(b0), "r"(b1))
#define CPASYNC16(dst, src) \
    asm volatile("cp.async.cg.shared.global [%0], [%1], 16;" :: "r"(dst), "l"(src))
#define CPCOMMIT() asm volatile("cp.async.commit_group;" ::: "memory")
#define CPWAIT0()  asm volatile("cp.async.wait_group 0;" ::: "memory")

__device__ __forceinline__ unsigned fenc(float f) {   // monotone float->uint
    int b = __float_as_int(f);
    return (b >= 0) ? ((unsigned)b | 0x80000000u) : ~(unsigned)b;
}
__device__ __forceinline__ float fdec(unsigned k) {
    int b = (k & 0x80000000u) ? (int)(k ^ 0x80000000u) : (int)~k;
    return __int_as_float(b);
}

// =====================================================================
// k_cvtW: W[k][d] fp32 -> g_WTh[d][k] fp16. 32 blocks x 256.
// =====================================================================
__global__ void __launch_bounds__(256) k_cvtW(const float* __restrict__ W)
{
    int gid = blockIdx.x * 256 + threadIdx.x;
    int k  = gid >> 5;
    int d4 = (gid & 31) * 4;
    float4 v = *(const float4*)&W[k * DOUT + d4];
    g_WTh[(d4 + 0) * DIN + k] = __float2half(v.x);
    g_WTh[(d4 + 1) * DIN + k] = __float2half(v.y);
    g_WTh[(d4 + 2) * DIN + k] = __float2half(v.z);
    g_WTh[(d4 + 3) * DIN + k] = __float2half(v.w);
}

// =====================================================================
// k_linear_h: HMMA x@W + bW. (unchanged from R8)
// =====================================================================
#define LXS    0
#define LWT    33792
#define LHS    0
#define LSRED  101376
#define LSMAX  103424
#define LDYN   103440

__global__ void __launch_bounds__(256) k_linear_h(
    const float* __restrict__ x, const float* __restrict__ bW,
    const float* __restrict__ a1, const float* __restrict__ a2)
{
    extern __shared__ char smem[];
    const uint32_t sb = smem_u32(smem);

    const int tid = threadIdx.x;
    const int wid = tid >> 5, lane = tid & 31;
    const int wm = wid & 1, wn = wid >> 1;
    const int row0 = blockIdx.x * 64;

#pragma unroll
    for (int m = 0; m < 32; m++) {
        int idx = tid + 256 * m;
        int r = idx >> 7, kk2 = idx & 127;
        float2 v = *(const float2*)&x[(size_t)(row0 + r) * DIN + kk2 * 2];
        __half2 h2 = __floats2half2_rn(v.x, v.y);
        *(uint32_t*)(smem + LXS + r * 528 + kk2 * 4) = *(uint32_t*)&h2;
    }
    {
        const int dd = tid >> 1, qq = tid & 1;
        const __half* src = g_WTh + dd * DIN + qq * 128;
        uint32_t dst = sb + LWT + dd * 528 + qq * 256;
#pragma unroll
        for (int i = 0; i < 16; i++) CPASYNC16(dst + i * 16, src + i * 8);
        CPCOMMIT();
    }
    CPWAIT0();
    __syncthreads();

    float acc[2][4][4];
#pragma unroll
    for (int mt = 0; mt < 2; mt++)
#pragma unroll
        for (int nt = 0; nt < 4; nt++)
#pragma unroll
            for (int k = 0; k < 4; k++) acc[mt][nt][k] = 0.f;

    const int mi = lane >> 3, r8 = lane & 7;
#pragma unroll
    for (int ks = 0; ks < 16; ks++) {
        uint32_t a[2][4];
#pragma unroll
        for (int mt = 0; mt < 2; mt++) {
            int arow = wm * 32 + mt * 16 + ((mi & 1) ? 8 : 0) + r8;
            int acol = ks * 16 + ((mi >> 1) ? 8 : 0);
            LDMX4(a[mt][0], a[mt][1], a[mt][2], a[mt][3],
                  sb + LXS + arow * 528 + acol * 2);
        }
        uint32_t bfr[4][2];
        {
            int nrow = wn * 32 + (mi >> 1) * 8 + r8;
            int bcol = ks * 16 + ((mi & 1) ? 8 : 0);
            LDMX4(bfr[0][0], bfr[0][1], bfr[1][0], bfr[1][1],
                  sb + LWT + nrow * 528 + bcol * 2);
            LDMX4(bfr[2][0], bfr[2][1], bfr[3][0], bfr[3][1],
                  sb + LWT + (nrow + 16) * 528 + bcol * 2);
        }
#pragma unroll
        for (int mt = 0; mt < 2; mt++)
#pragma unroll
            for (int nt = 0; nt < 4; nt++)
                MMA16816(acc[mt][nt], a[mt][0], a[mt][1], a[mt][2], a[mt][3],
                         bfr[nt][0], bfr[nt][1]);
    }
    __syncthreads();

    float* sred = (float*)(smem + LSRED);
    float s1p[4] = {0.f, 0.f, 0.f, 0.f};
    float s2p[4] = {0.f, 0.f, 0.f, 0.f};
    const int ra0 = wm * 32 + (lane >> 2);
#pragma unroll
    for (int mt = 0; mt < 2; mt++) {
        const int r_a = ra0 + mt * 16, r_b = r_a + 8;
#pragma unroll
        for (int nt = 0; nt < 4; nt++) {
            const int c0 = wn * 32 + nt * 8 + (lane & 3) * 2;
            float2 bw2 = *(const float2*)&bW[c0];
            float2 a12 = *(const float2*)&a1[c0];
            float2 a22 = *(const float2*)&a2[c0];
            float h0 = acc[mt][nt][0] + bw2.x, h1 = acc[mt][nt][1] + bw2.y;
            float h2 = acc[mt][nt][2] + bw2.x, h3 = acc[mt][nt][3] + bw2.y;
            s1p[mt * 2 + 0] += h0 * a12.x + h1 * a12.y;
            s2p[mt * 2 + 0] += h0 * a22.x + h1 * a22.y;
            s1p[mt * 2 + 1] += h2 * a12.x + h3 * a12.y;
            s2p[mt * 2 + 1] += h2 * a22.x + h3 * a22.y;
            *(__half*)(smem + LHS + (c0    ) * 144 + r_a * 2) = __float2half(h0);
            *(__half*)(smem + LHS + (c0 + 1) * 144 + r_a * 2) = __float2half(h1);
            *(__half*)(smem + LHS + (c0    ) * 144 + r_b * 2) = __float2half(h2);
            *(__half*)(smem + LHS + (c0 + 1) * 144 + r_b * 2) = __float2half(h3);
        }
    }
#pragma unroll
    for (int t = 0; t < 4; t++) {
        s1p[t] += __shfl_xor_sync(0xffffffffu, s1p[t], 1);
        s1p[t] += __shfl_xor_sync(0xffffffffu, s1p[t], 2);
        s2p[t] += __shfl_xor_sync(0xffffffffu, s2p[t], 1);
        s2p[t] += __shfl_xor_sync(0xffffffffu, s2p[t], 2);
    }
    if ((lane & 3) == 0) {
#pragma unroll
        for (int mt = 0; mt < 2; mt++) {
            const int r_a = ra0 + mt * 16, r_b = r_a + 8;
            sred[r_a * 8 + wn]     = s1p[mt * 2 + 0];
            sred[r_a * 8 + 4 + wn] = s2p[mt * 2 + 0];
            sred[r_b * 8 + wn]     = s1p[mt * 2 + 1];
            sred[r_b * 8 + 4 + wn] = s2p[mt * 2 + 1];
        }
    }
    __syncthreads();

    {
        const int dd = tid >> 1, qq = tid & 1;
        const char* src = smem + LHS + dd * 144 + qq * 64;
        __half* dst = g_hT + (size_t)dd * NN + row0 + qq * 32;
#pragma unroll
        for (int i = 0; i < 4; i++)
            *(uint4*)(dst + i * 8) = *(const uint4*)(src + i * 16);
    }
    if (tid < 64) {
        float S1 = sred[tid * 8 + 0] + sred[tid * 8 + 1] + sred[tid * 8 + 2] + sred[tid * 8 + 3];
        float S2 = sred[tid * 8 + 4] + sred[tid * 8 + 5] + sred[tid * 8 + 6] + sred[tid * 8 + 7];
        g_ssrc[row0 + tid] = S1;
        g_sdst[row0 + tid] = S2;
        float mx = S2;
#pragma unroll
        for (int off = 16; off > 0; off >>= 1)
            mx = fmaxf(mx, __shfl_xor_sync(0xffffffffu, mx, off));
        if (lane == 0) ((float*)(smem + LSMAX))[tid >> 5] = mx;
    }
    __syncthreads();
    if (tid == 0) {
        float m = fmaxf(((float*)(smem + LSMAX))[0], ((float*)(smem + LSMAX))[1]);
        atomicMax(&g_Vu, fenc(m));
    }
}

// =====================================================================
__global__ void k_prep(const float* __restrict__ ba)
{
    int i = blockIdx.x * blockDim.x + threadIdx.x;
    if (i >= NN) return;
    const float V = fdec(g_Vu);
    float u = g_ssrc[i] + ba[0];
    float t = u + V;
    float c = fmaxf(t, 0.01f * t);
    g_Ah[i] = __float2half(expf(t - c));
    g_Bh[i] = __float2half(expf(0.01f * t - c));
    float v = g_sdst[i] - V;
    g_ph[i] = __float2half(expf(v));
    g_qh[i] = __float2half(expf(0.01f * v));
}

// =====================================================================
// k_main_m: fused HMMA masked GEMM. CTA = 256 thr (8 warps 2m x 4n),
// 64 i x 128 d over a 1024-j segment in 64-j chunks.
// R9: gen = 4 rows x 4 j per thread (LDG.128 adj, STS.64 w); A/B in
// regs; p/q staged in smem per segment; denominator accumulated on
// the gen side (no ones-MMA); atomic epilogue.
// =====================================================================
#define WSTB   144
#define SM_W0  0
#define SM_W1  (RT * WSTB)              // 9216
#define SM_H0  (2 * RT * WSTB)          // 18432
#define SM_H1  (SM_H0 + 128 * WSTB)     // 36864
#define SM_PS  (SM_H1 + 128 * WSTB)     // 55296 (2048B: seg p as half)
#define SM_QS  (SM_PS + 2048)           // 57344 (2048B: seg q)
#define SM_DYN (SM_QS + 2048 + 64)

__global__ void __launch_bounds__(256, 3) k_main_m(const int* __restrict__ adj)
{
    extern __shared__ char smem[];
    const uint32_t sb = smem_u32(smem);

    const int tid  = threadIdx.x;
    const int wid  = tid >> 5, lane = tid & 31;
    const int rt   = blockIdx.x & 127;
    const int seg  = blockIdx.x >> 7;
    const int row0 = rt * RT;
    const int j0   = seg * SEG;

    const int jq  = tid & 15;          // j quad: j = jq*4
    const int rg4 = tid >> 4;          // rows rg4*4 .. rg4*4+3
    const int dd  = tid >> 1, qq = tid & 1;
    const int wm  = wid & 1, wn = wid >> 1;

    // ---- stage p/q for the whole segment (once) ----
    ((uint2*)(smem + SM_PS))[tid] = ((const uint2*)(g_ph + j0))[tid];
    ((uint2*)(smem + SM_QS))[tid] = ((const uint2*)(g_qh + j0))[tid];

    // ---- A/B for this thread's 4 rows, in registers ----
    __half2 A2[4], B2[4];
#pragma unroll
    for (int k = 0; k < 4; k++) {
        A2[k] = __half2half2(g_Ah[row0 + rg4 * 4 + k]);
        B2[k] = __half2half2(g_Bh[row0 + rg4 * 4 + k]);
    }

    float acc[2][4][4];
#pragma unroll
    for (int mt = 0; mt < 2; mt++)
#pragma unroll
        for (int nt = 0; nt < 4; nt++)
#pragma unroll
            for (int k = 0; k < 4; k++) acc[mt][nt][k] = 0.f;
    float dacc[4] = {0.f, 0.f, 0.f, 0.f};

    // ---- prologue: stage h[0], prefetch adj[0] ----
    int4 adjc[4];
    {
        const __half* hs = g_hT + (size_t)dd * NN + j0 + qq * 32;
        uint32_t hd = sb + SM_H0 + dd * WSTB + qq * 64;
#pragma unroll
        for (int k = 0; k < 4; k++) CPASYNC16(hd + 16 * k, hs + 8 * k);
        CPCOMMIT();
        const int* ap = adj + (size_t)(row0 + rg4 * 4) * NN + j0 + jq * 4;
#pragma unroll
        for (int k = 0; k < 4; k++) adjc[k] = *(const int4*)(ap + (size_t)k * NN);
    }
    __syncthreads();   // p/q staging visible

    for (int c = 0; c < NCH; c++) {
        const int b = c & 1;
        const uint32_t wb = sb + (b ? SM_W1 : SM_W0);
        const uint32_t hb = sb + (b ? SM_H1 : SM_H0);

        // ---- generate w tile: 4 rows x 4 j per thread ----
        {
            uint2 pr = *(const uint2*)(smem + SM_PS + c * 128 + jq * 8);
            uint2 qr = *(const uint2*)(smem + SM_QS + c * 128 + jq * 8);
            const __half2 p01 = ((const __half2*)&pr)[0];
            const __half2 p23 = ((const __half2*)&pr)[1];
            const __half2 q01 = ((const __half2*)&qr)[0];
            const __half2 q23 = ((const __half2*)&qr)[1];
#pragma unroll
            for (int k = 0; k < 4; k++) {
                uint32_t m01 = (uint32_t)(adjc[k].x | (adjc[k].y << 16)) * 0xFFFFu;
                uint32_t m23 = (uint32_t)(adjc[k].z | (adjc[k].w << 16)) * 0xFFFFu;
                __half2 w01 = __hmax2(__hmul2(A2[k], p01), __hmul2(B2[k], q01));
                __half2 w23 = __hmax2(__hmul2(A2[k], p23), __hmul2(B2[k], q23));
                uint32_t u01 = (*(uint32_t*)&w01) & m01;
                uint32_t u23 = (*(uint32_t*)&w23) & m23;
                *(uint2*)(smem + (b ? SM_W1 : SM_W0) + (rg4 * 4 + k) * WSTB + jq * 8)
                    = make_uint2(u01, u23);
                __half2 hs2 = __hadd2(*(__half2*)&u01, *(__half2*)&u23);
                dacc[k] += __low2float(hs2) + __high2float(hs2);
            }
        }
        CPWAIT0();
        __syncthreads();

        // ---- prefetch chunk c+1 ----
        if (c + 1 < NCH) {
            const int jb1 = j0 + (c + 1) * KC;
            const __half* hs = g_hT + (size_t)dd * NN + jb1 + qq * 32;
            uint32_t hd = sb + (b ? SM_H0 : SM_H1) + dd * WSTB + qq * 64;
#pragma unroll
            for (int k = 0; k < 4; k++) CPASYNC16(hd + 16 * k, hs + 8 * k);
            CPCOMMIT();
            const int* ap = adj + (size_t)(row0 + rg4 * 4) * NN + jb1 + jq * 4;
#pragma unroll
            for (int k = 0; k < 4; k++) adjc[k] = *(const int4*)(ap + (size_t)k * NN);
        }

        // ---- MMA: 4 k-steps ----
        const int mi = lane >> 3, r8 = lane & 7;
#pragma unroll
        for (int ks = 0; ks < 4; ks++) {
            uint32_t a[2][4];
#pragma unroll
            for (int mt = 0; mt < 2; mt++) {
                int arow = wm * 32 + mt * 16 + ((mi & 1) ? 8 : 0) + r8;
                int acol = ks * 16 + ((mi >> 1) ? 8 : 0);
                LDMX4(a[mt][0], a[mt][1], a[mt][2], a[mt][3],
                      wb + arow * WSTB + acol * 2);
            }
            uint32_t bfr[4][2];
            {
                int nrow = wn * 32 + (mi >> 1) * 8 + r8;
                int bcol = ks * 16 + ((mi & 1) ? 8 : 0);
                LDMX4(bfr[0][0], bfr[0][1], bfr[1][0], bfr[1][1],
                      hb + nrow * WSTB + bcol * 2);
                LDMX4(bfr[2][0], bfr[2][1], bfr[3][0], bfr[3][1],
                      hb + (nrow + 16) * WSTB + bcol * 2);
            }
#pragma unroll
            for (int mt = 0; mt < 2; mt++)
#pragma unroll
                for (int nt = 0; nt < 4; nt++)
                    MMA16816(acc[mt][nt], a[mt][0], a[mt][1], a[mt][2], a[mt][3],
                             bfr[nt][0], bfr[nt][1]);
        }
    }

    // ---- denominator: reduce over the 16 jq lanes (width-16) ----
#pragma unroll
    for (int k = 0; k < 4; k++) {
        float d = dacc[k];
#pragma unroll
        for (int off = 8; off > 0; off >>= 1)
            d += __shfl_xor_sync(0xffffffffu, d, off, 16);
        if (jq == 0)
            atomicAdd(&g_den[row0 + rg4 * 4 + k], d);
    }

    // ---- epilogue: atomic accumulation of numerator ----
    const int rlo = row0 + wm * 32 + (lane >> 2);
    const int col = wn * 32 + (lane & 3) * 2;
#pragma unroll
    for (int mt = 0; mt < 2; mt++) {
#pragma unroll
        for (int nt = 0; nt < 4; nt++) {
            float* p0 = &g_num[(size_t)(rlo + mt * 16) * DOUT + nt * 8 + col];
            float* p1 = &g_num[(size_t)(rlo + mt * 16 + 8) * DOUT + nt * 8 + col];
            atomicAdd(p0,     acc[mt][nt][0]);
            atomicAdd(p0 + 1, acc[mt][nt][1]);
            atomicAdd(p1,     acc[mt][nt][2]);
            atomicAdd(p1 + 1, acc[mt][nt][3]);
        }
    }
}

// =====================================================================
// k_combine: out = num/den, restore scratch to zero.
// =====================================================================
__global__ void __launch_bounds__(256) k_combine(float* __restrict__ out)
{
    const int idx = blockIdx.x * 256 + threadIdx.x;
    const int i  = idx >> 5;
    const int dq = idx & 31;
    float4 v = *(const float4*)&g_num[(size_t)i * DOUT + dq * 4];
    float den = g_den[i];
    __syncwarp();
    if (dq == 0) g_den[i] = 0.f;
    *(float4*)&g_num[(size_t)i * DOUT + dq * 4] = make_float4(0.f, 0.f, 0.f, 0.f);
    const float inv = 1.0f / fmaxf(den, 1e-30f);
    v.x *= inv; v.y *= inv; v.z *= inv; v.w *= inv;
    *(float4*)&out[(size_t)i * DOUT + dq * 4] = v;
    if (idx == 0) g_Vu = 0u;
}

// =====================================================================
extern "C" void kernel_launch(void* const* d_in, const int* in_sizes, int n_in,
                              void* d_out, int out_size)
{
    const float* x   = (const float*)d_in[0];
    const int*   adj = (const int*)  d_in[1];
    const float* W   = (const float*)d_in[2];
    const float* bW  = (const float*)d_in[3];
    const float* a1  = (const float*)d_in[4];
    const float* a2  = (const float*)d_in[5];
    const float* ba  = (const float*)d_in[6];
    float* out = (float*)d_out;

    cudaFuncSetAttribute(k_linear_h, cudaFuncAttributeMaxDynamicSharedMemorySize, LDYN);
    cudaFuncSetAttribute(k_main_m, cudaFuncAttributeMaxDynamicSharedMemorySize, SM_DYN);

    k_cvtW<<<32, 256>>>(W);
    k_linear_h<<<NN / 64, 256, LDYN>>>(x, bW, a1, a2);
    k_prep<<<NN / 256, 256>>>(ba);
    k_main_m<<<128 * JS, 256, SM_DYN>>>(adj);
    k_combine<<<NN * DOUT / 4 / 256, 256>>>(out);
}